// round 16
// baseline (speedup 1.0000x reference)
#include <cuda_runtime.h>
#include <cuda_fp16.h>
#include <cstdint>

#define DEVINL __device__ __forceinline__

namespace {

constexpr int BATCH = 32;
constexpr int LSEQ  = 8192;
constexpr int THREADS = 512;                 // 16 independent warps
constexpr int GRID = 152;                    // 1 CTA per SM
constexpr int STRIPS_PER_BATCH = LSEQ / 32;  // 256 32-row strips
constexpr float LOG2E = 1.4426950408889634f;

// ---- SMEM layout (bytes) ----
constexpr int SM_KSUM = 0;                   // 128 floats
constexpr int SM_KH   = 1024;                // 128x128 fp16, XOR-swizzled (k-permuted rows)
constexpr int SM_KL   = SM_KH + 32768;
constexpr int SM_VH   = SM_KL + 32768;
constexpr int SMEM_TOTAL = SM_VH + 32768;    // 99328 B

// byte offset of fp16 element (r, c) in a tile with 256B rows; XOR swizzle
DEVINL uint32_t swz(int r, int c) {
    return (uint32_t)((r << 8) | ((((c >> 3) ^ (r & 7)) << 4) | ((c & 7) << 1)));
}

// contraction-dim permutation (see R8): orig o = 4t+2b+d -> pos 8b+2t+d per 16-block
DEVINL int kperm(int r) {
    int o = r & 15;
    return (r & 112) | ((o & 2) << 2) | ((o & 12) >> 1) | (o & 1);
}

DEVINL uint32_t smem_u32(const void* p) {
    uint32_t a;
    asm("{ .reg .u64 t; cvta.to.shared.u64 t, %1; cvt.u32.u64 %0, t; }" : "=r"(a) : "l"(p));
    return a;
}

DEVINL uint32_t packh(__half a, __half b) {
    return (uint32_t)__half_as_ushort(a) | ((uint32_t)__half_as_ushort(b) << 16);
}

DEVINL void split_pack2h(float a, float b, uint32_t& h, uint32_t& l) {
    __half ha = __float2half_rn(a), hb = __float2half_rn(b);
    __half la = __float2half_rn(a - __half2float(ha));
    __half lb = __float2half_rn(b - __half2float(hb));
    h = packh(ha, hb);
    l = packh(la, lb);
}
DEVINL uint32_t pack_hi2(float a, float b) {
    return packh(__float2half_rn(a), __float2half_rn(b));
}
DEVINL uint32_t hmul2u(uint32_t a, uint32_t b) {
    __half2 ha = *reinterpret_cast<__half2*>(&a);
    __half2 hb = *reinterpret_cast<__half2*>(&b);
    __half2 hr = __hmul2(ha, hb);
    return *reinterpret_cast<uint32_t*>(&hr);
}
DEVINL float ex2f(float x) {
    float r;
    asm("ex2.approx.ftz.f32 %0, %1;" : "=f"(r) : "f"(x));
    return r;
}

// ldmatrix x4 address into a 256B-row swizzled tile
DEVINL uint32_t ldsm_addr(uint32_t tbase, int rbase, int c8base, int lane) {
    int ln = lane & 7, sel = lane >> 3;
    int r  = rbase + ln + ((sel & 1) << 3);
    int c8 = c8base + (sel >> 1);
    return tbase + swz(r, c8 << 3);
}

DEVINL void ldsm4t(uint32_t a[4], uint32_t addr) {
    asm volatile("ldmatrix.sync.aligned.m8n8.x4.trans.shared.b16 {%0,%1,%2,%3}, [%4];"
                 : "=r"(a[0]), "=r"(a[1]), "=r"(a[2]), "=r"(a[3]) : "r"(addr));
}

DEVINL void mma_fp16(float c[4], const uint32_t a[4], uint32_t b0, uint32_t b1) {
    asm volatile(
        "mma.sync.aligned.m16n8k16.row.col.f32.f16.f16.f32 "
        "{%0,%1,%2,%3}, {%4,%5,%6,%7}, {%8,%9}, {%0,%1,%2,%3};"
        : "+f"(c[0]), "+f"(c[1]), "+f"(c[2]), "+f"(c[3])
        : "r"(a[0]), "r"(a[1]), "r"(a[2]), "r"(a[3]), "r"(b0), "r"(b1));
}

__global__ void __launch_bounds__(THREADS, 1)
axial_attn_kernel(const float* __restrict__ q, const float* __restrict__ k,
                  const float* __restrict__ v, float* __restrict__ out) {
    extern __shared__ char smem[];
    const uint32_t sb = smem_u32(smem);
    const int tid  = threadIdx.x;
    const int lane = tid & 31, w = tid >> 5;
    const int g = lane >> 2, t = lane & 3;

    // ---- CTA -> (batch, strip chunk). 152 = 24*5 + 8*4 ----
    int bx = blockIdx.x;
    int batch, cidx, ncta;
    if (bx < 120) { batch = bx / 5; cidx = bx - batch * 5; ncta = 5; }
    else { int r = bx - 120; int bb = r >> 2; batch = 24 + bb; cidx = r & 3; ncta = 4; }
    const int base = STRIPS_PER_BATCH / ncta, rem = STRIPS_PER_BATCH - base * ncta;
    int sstart, scnt;
    if (cidx < rem) { scnt = base + 1; sstart = cidx * scnt; }
    else            { scnt = base;     sstart = rem * (base + 1) + (cidx - rem) * base; }

    float* ksum = reinterpret_cast<float*>(smem + SM_KSUM);

    const float* kb = k + (size_t)batch * (128 * 128);
    const float* vb = v + (size_t)batch * (128 * 128);

    // ======== one-time fill: K (hi/lo, permuted contraction rows, + row sums), V (hi) ========
    {
        const float4* kb4 = reinterpret_cast<const float4*>(kb);
        #pragma unroll 4
        for (int it = 0; it < 8; it++) {
            int e4  = it * THREADS + tid;          // warp covers exactly one row
            int row = e4 >> 5;
            int col = (e4 & 31) << 2;
            float4 tk = kb4[e4];
            uint32_t h01, l01, h23, l23;
            split_pack2h(tk.x, tk.y, h01, l01);
            split_pack2h(tk.z, tk.w, h23, l23);
            uint32_t off = swz(kperm(row), col);
            *reinterpret_cast<uint2*>(smem + SM_KH + off) = make_uint2(h01, h23);
            *reinterpret_cast<uint2*>(smem + SM_KL + off) = make_uint2(l01, l23);
            float s = (tk.x + tk.y) + (tk.z + tk.w);
            s += __shfl_xor_sync(0xffffffffu, s, 16);
            s += __shfl_xor_sync(0xffffffffu, s, 8);
            s += __shfl_xor_sync(0xffffffffu, s, 4);
            s += __shfl_xor_sync(0xffffffffu, s, 2);
            s += __shfl_xor_sync(0xffffffffu, s, 1);
            if (lane == 0) ksum[row] = s;
        }
        const float4* vb4 = reinterpret_cast<const float4*>(vb);
        #pragma unroll 4
        for (int it = 0; it < 8; it++) {
            int e4  = it * THREADS + tid;
            int row = e4 >> 5;
            int col = (e4 & 31) << 2;
            float4 tv = vb4[e4];
            uint32_t off = swz(row, col);
            *reinterpret_cast<uint2*>(smem + SM_VH + off) =
                make_uint2(pack_hi2(tv.x, tv.y), pack_hi2(tv.z, tv.w));
        }
    }
    __syncthreads();

    // ======== per-warp strip loop (32 rows x 128 cols; no barriers) ========
    // thread rows: g (m0 lo), g+8 (m0 hi), g+16 (m1 lo), g+24 (m1 hi)
    for (int s = w; s < scnt; s += 16) {
        const int r0 = (sstart + s) * 32;
        const float* qrw = q + ((size_t)batch * LSEQ + r0 + g) * 128 + 4 * t;

        float mloc[2][4], sloc[2][4];
        uint32_t A2[2][2][4][4];   // [phase][m][kk_local][reg] — unnormalized exp, fp16
        float qs[4];

        // ---- GEMM1 in two 64-col phases (online softmax) ----
        #pragma unroll
        for (int ph = 0; ph < 2; ph++) {
            float C1[2][8][4];     // [m][jt][i], 64 cols
            #pragma unroll
            for (int m = 0; m < 2; m++)
                #pragma unroll
                for (int jt = 0; jt < 8; jt++)
                    #pragma unroll
                    for (int i = 0; i < 4; i++) C1[m][jt][i] = 0.f;

            if (ph == 0) { qs[0] = qs[1] = qs[2] = qs[3] = 0.f; }

            #pragma unroll
            for (int kk = 0; kk < 8; kk++) {
                float4 qa = *reinterpret_cast<const float4*>(qrw + 16 * kk);
                float4 qb = *reinterpret_cast<const float4*>(qrw + 8 * 128 + 16 * kk);
                float4 qc = *reinterpret_cast<const float4*>(qrw + 16 * 128 + 16 * kk);
                float4 qd = *reinterpret_cast<const float4*>(qrw + 24 * 128 + 16 * kk);
                if (ph == 0) {
                    qs[0] += (qa.x + qa.y) + (qa.z + qa.w);
                    qs[1] += (qb.x + qb.y) + (qb.z + qb.w);
                    qs[2] += (qc.x + qc.y) + (qc.z + qc.w);
                    qs[3] += (qd.x + qd.y) + (qd.z + qd.w);
                }
                // scale by log2e before the split: MMA computes (log2e*Q)*K
                uint32_t A0h[4], A0l[4], A1h[4], A1l[4];
                split_pack2h(qa.x * LOG2E, qa.y * LOG2E, A0h[0], A0l[0]);
                split_pack2h(qb.x * LOG2E, qb.y * LOG2E, A0h[1], A0l[1]);
                split_pack2h(qa.z * LOG2E, qa.w * LOG2E, A0h[2], A0l[2]);
                split_pack2h(qb.z * LOG2E, qb.w * LOG2E, A0h[3], A0l[3]);
                split_pack2h(qc.x * LOG2E, qc.y * LOG2E, A1h[0], A1l[0]);
                split_pack2h(qd.x * LOG2E, qd.y * LOG2E, A1h[1], A1l[1]);
                split_pack2h(qc.z * LOG2E, qc.w * LOG2E, A1h[2], A1l[2]);
                split_pack2h(qd.z * LOG2E, qd.w * LOG2E, A1h[3], A1l[3]);

                #pragma unroll
                for (int jp = 0; jp < 4; jp++) {
                    const int c8 = 8 * ph + 2 * jp;
                    uint32_t bh[4], bl[4];
                    ldsm4t(bh, ldsm_addr(sb + SM_KH, 16 * kk, c8, lane));
                    ldsm4t(bl, ldsm_addr(sb + SM_KL, 16 * kk, c8, lane));
                    // m-block 0
                    mma_fp16(C1[0][2 * jp],     A0h, bh[0], bh[1]);
                    mma_fp16(C1[0][2 * jp + 1], A0h, bh[2], bh[3]);
                    mma_fp16(C1[0][2 * jp],     A0h, bl[0], bl[1]);
                    mma_fp16(C1[0][2 * jp + 1], A0h, bl[2], bl[3]);
                    mma_fp16(C1[0][2 * jp],     A0l, bh[0], bh[1]);
                    mma_fp16(C1[0][2 * jp + 1], A0l, bh[2], bh[3]);
                    // m-block 1 (same B fragments)
                    mma_fp16(C1[1][2 * jp],     A1h, bh[0], bh[1]);
                    mma_fp16(C1[1][2 * jp + 1], A1h, bh[2], bh[3]);
                    mma_fp16(C1[1][2 * jp],     A1h, bl[0], bl[1]);
                    mma_fp16(C1[1][2 * jp + 1], A1h, bl[2], bl[3]);
                    mma_fp16(C1[1][2 * jp],     A1l, bh[0], bh[1]);
                    mma_fp16(C1[1][2 * jp + 1], A1l, bh[2], bh[3]);
                }
            }

            if (ph == 0) {
                #pragma unroll
                for (int r = 0; r < 4; r++) {
                    qs[r] += __shfl_xor_sync(0xffffffffu, qs[r], 1);
                    qs[r] += __shfl_xor_sync(0xffffffffu, qs[r], 2);
                    qs[r] *= LOG2E;     // rank-1 term in base-2 domain
                }
            }

            // ---- exact rank-1 term for this phase's 64 cols ----
            #pragma unroll
            for (int jt = 0; jt < 8; jt++) {
                float2 ks2 = *reinterpret_cast<const float2*>(ksum + 64 * ph + 8 * jt + 2 * t);
                C1[0][jt][0] += qs[0] * ks2.x;
                C1[0][jt][1] += qs[0] * ks2.y;
                C1[0][jt][2] += qs[1] * ks2.x;
                C1[0][jt][3] += qs[1] * ks2.y;
                C1[1][jt][0] += qs[2] * ks2.x;
                C1[1][jt][1] += qs[2] * ks2.y;
                C1[1][jt][2] += qs[3] * ks2.x;
                C1[1][jt][3] += qs[3] * ks2.y;
            }

            // ---- local softmax (base 2) over this phase's 64 cols ----
            #pragma unroll
            for (int m = 0; m < 2; m++) {
                float a = -3.4e38f, b = -3.4e38f;
                #pragma unroll
                for (int jt = 0; jt < 8; jt++) {
                    a = fmaxf(a, fmaxf(C1[m][jt][0], C1[m][jt][1]));
                    b = fmaxf(b, fmaxf(C1[m][jt][2], C1[m][jt][3]));
                }
                a = fmaxf(a, __shfl_xor_sync(0xffffffffu, a, 1));
                a = fmaxf(a, __shfl_xor_sync(0xffffffffu, a, 2));
                b = fmaxf(b, __shfl_xor_sync(0xffffffffu, b, 1));
                b = fmaxf(b, __shfl_xor_sync(0xffffffffu, b, 2));
                float sa = 0.f, sbv = 0.f;
                #pragma unroll
                for (int jt = 0; jt < 8; jt++) {
                    C1[m][jt][0] = ex2f(C1[m][jt][0] - a);
                    C1[m][jt][1] = ex2f(C1[m][jt][1] - a);
                    C1[m][jt][2] = ex2f(C1[m][jt][2] - b);
                    C1[m][jt][3] = ex2f(C1[m][jt][3] - b);
                    sa  += C1[m][jt][0] + C1[m][jt][1];
                    sbv += C1[m][jt][2] + C1[m][jt][3];
                }
                sa  += __shfl_xor_sync(0xffffffffu, sa, 1);
                sa  += __shfl_xor_sync(0xffffffffu, sa, 2);
                sbv += __shfl_xor_sync(0xffffffffu, sbv, 1);
                sbv += __shfl_xor_sync(0xffffffffu, sbv, 2);
                mloc[ph][2 * m]     = a;  sloc[ph][2 * m]     = sa;
                mloc[ph][2 * m + 1] = b;  sloc[ph][2 * m + 1] = sbv;
            }

            // ---- pack unnormalized exp as A-fragments (GEMM2 k-blocks 4*ph..4*ph+3) ----
            #pragma unroll
            for (int m = 0; m < 2; m++)
                #pragma unroll
                for (int kl = 0; kl < 4; kl++) {
                    A2[ph][m][kl][0] = pack_hi2(C1[m][2 * kl][0],     C1[m][2 * kl][1]);
                    A2[ph][m][kl][1] = pack_hi2(C1[m][2 * kl][2],     C1[m][2 * kl][3]);
                    A2[ph][m][kl][2] = pack_hi2(C1[m][2 * kl + 1][0], C1[m][2 * kl + 1][1]);
                    A2[ph][m][kl][3] = pack_hi2(C1[m][2 * kl + 1][2], C1[m][2 * kl + 1][3]);
                }
        }

        // ---- merge phases: per-row factors exp2(m_loc - M) / sum_total ----
        uint32_t F[2][2][2];   // [phase][m][rowhalf]
        #pragma unroll
        for (int r = 0; r < 4; r++) {
            const float M = fmaxf(mloc[0][r], mloc[1][r]);
            const float e0 = ex2f(mloc[0][r] - M);
            const float e1 = ex2f(mloc[1][r] - M);
            const float inv = 1.0f / (sloc[0][r] * e0 + sloc[1][r] * e1);
            const float f0 = e0 * inv, f1 = e1 * inv;
            F[0][r >> 1][r & 1] = pack_hi2(f0, f0);
            F[1][r >> 1][r & 1] = pack_hi2(f1, f1);
        }
        #pragma unroll
        for (int ph = 0; ph < 2; ph++)
            #pragma unroll
            for (int m = 0; m < 2; m++)
                #pragma unroll
                for (int kl = 0; kl < 4; kl++) {
                    A2[ph][m][kl][0] = hmul2u(A2[ph][m][kl][0], F[ph][m][0]);
                    A2[ph][m][kl][1] = hmul2u(A2[ph][m][kl][1], F[ph][m][1]);
                    A2[ph][m][kl][2] = hmul2u(A2[ph][m][kl][2], F[ph][m][0]);
                    A2[ph][m][kl][3] = hmul2u(A2[ph][m][kl][3], F[ph][m][1]);
                }

        // ---- GEMM2 in four 32-col d-quarters: O = P @ Vh (V frags shared by 2 m-blocks) ----
        #pragma unroll
        for (int dq = 0; dq < 4; dq++) {
            float C2[2][4][4];
            #pragma unroll
            for (int m = 0; m < 2; m++)
                #pragma unroll
                for (int jt = 0; jt < 4; jt++)
                    #pragma unroll
                    for (int i = 0; i < 4; i++) C2[m][jt][i] = 0.f;

            #pragma unroll
            for (int kk = 0; kk < 8; kk++) {
                const int ph = kk >> 2, kl = kk & 3;
                #pragma unroll
                for (int jp = 0; jp < 2; jp++) {
                    uint32_t bh[4];
                    ldsm4t(bh, ldsm_addr(sb + SM_VH, 16 * kk, 4 * dq + 2 * jp, lane));
                    mma_fp16(C2[0][2 * jp],     A2[ph][0][kl], bh[0], bh[1]);
                    mma_fp16(C2[0][2 * jp + 1], A2[ph][0][kl], bh[2], bh[3]);
                    mma_fp16(C2[1][2 * jp],     A2[ph][1][kl], bh[0], bh[1]);
                    mma_fp16(C2[1][2 * jp + 1], A2[ph][1][kl], bh[2], bh[3]);
                }
            }

            // ---- store this quarter ----
            #pragma unroll
            for (int m = 0; m < 2; m++) {
                float* og = out + ((size_t)batch * LSEQ + r0 + 16 * m) * 128 + 32 * dq;
                #pragma unroll
                for (int jt = 0; jt < 4; jt++) {
                    const int col = 8 * jt + 2 * t;
                    *reinterpret_cast<float2*>(og + (size_t)g * 128 + col) =
                        make_float2(C2[m][jt][0], C2[m][jt][1]);
                    *reinterpret_cast<float2*>(og + (size_t)(g + 8) * 128 + col) =
                        make_float2(C2[m][jt][2], C2[m][jt][3]);
                }
            }
        }
    }
}

} // anonymous namespace

extern "C" void kernel_launch(void* const* d_in, const int* in_sizes, int n_in,
                              void* d_out, int out_size) {
    const float* q = (const float*)d_in[0];
    const float* k = (const float*)d_in[1];
    const float* v = (const float*)d_in[2];
    float* out = (float*)d_out;

    cudaFuncSetAttribute(axial_attn_kernel,
                         cudaFuncAttributeMaxDynamicSharedMemorySize, SMEM_TOTAL);
    axial_attn_kernel<<<GRID, THREADS, SMEM_TOTAL>>>(q, k, v, out);
}

// round 17
// speedup vs baseline: 1.2213x; 1.2213x over previous
#include <cuda_runtime.h>
#include <cuda_fp16.h>
#include <cstdint>

#define DEVINL __device__ __forceinline__

namespace {

constexpr int BATCH = 32;
constexpr int LSEQ  = 8192;
constexpr int THREADS = 384;                 // 12 independent warps, 170 regs/thread
constexpr int NW = 12;
constexpr int GRID = 152;                    // 1 CTA per SM
constexpr int STRIPS_PER_BATCH = LSEQ / 32;  // 256 32-row strips
constexpr float LOG2E = 1.4426950408889634f;

// ---- SMEM layout (bytes) ----
constexpr int SM_KSUM = 0;                   // 128 floats
constexpr int SM_KH   = 1024;                // 128x128 fp16, XOR-swizzled (k-permuted rows)
constexpr int SM_KL   = SM_KH + 32768;
constexpr int SM_VH   = SM_KL + 32768;
constexpr int SMEM_TOTAL = SM_VH + 32768;    // 99328 B

// byte offset of fp16 element (r, c) in a tile with 256B rows; XOR swizzle
DEVINL uint32_t swz(int r, int c) {
    return (uint32_t)((r << 8) | ((((c >> 3) ^ (r & 7)) << 4) | ((c & 7) << 1)));
}

// contraction-dim permutation (see R8): orig o = 4t+2b+d -> pos 8b+2t+d per 16-block
DEVINL int kperm(int r) {
    int o = r & 15;
    return (r & 112) | ((o & 2) << 2) | ((o & 12) >> 1) | (o & 1);
}

DEVINL uint32_t smem_u32(const void* p) {
    uint32_t a;
    asm("{ .reg .u64 t; cvta.to.shared.u64 t, %1; cvt.u32.u64 %0, t; }" : "=r"(a) : "l"(p));
    return a;
}

DEVINL uint32_t packh(__half a, __half b) {
    return (uint32_t)__half_as_ushort(a) | ((uint32_t)__half_as_ushort(b) << 16);
}

DEVINL void split_pack2h(float a, float b, uint32_t& h, uint32_t& l) {
    __half ha = __float2half_rn(a), hb = __float2half_rn(b);
    __half la = __float2half_rn(a - __half2float(ha));
    __half lb = __float2half_rn(b - __half2float(hb));
    h = packh(ha, hb);
    l = packh(la, lb);
}
DEVINL uint32_t pack_hi2(float a, float b) {
    return packh(__float2half_rn(a), __float2half_rn(b));
}
DEVINL uint32_t hmul2u(uint32_t a, uint32_t b) {
    __half2 ha = *reinterpret_cast<__half2*>(&a);
    __half2 hb = *reinterpret_cast<__half2*>(&b);
    __half2 hr = __hmul2(ha, hb);
    return *reinterpret_cast<uint32_t*>(&hr);
}
DEVINL float ex2f(float x) {
    float r;
    asm("ex2.approx.ftz.f32 %0, %1;" : "=f"(r) : "f"(x));
    return r;
}

// ldmatrix x4 address into a 256B-row swizzled tile
DEVINL uint32_t ldsm_addr(uint32_t tbase, int rbase, int c8base, int lane) {
    int ln = lane & 7, sel = lane >> 3;
    int r  = rbase + ln + ((sel & 1) << 3);
    int c8 = c8base + (sel >> 1);
    return tbase + swz(r, c8 << 3);
}

DEVINL void ldsm4t(uint32_t a[4], uint32_t addr) {
    asm volatile("ldmatrix.sync.aligned.m8n8.x4.trans.shared.b16 {%0,%1,%2,%3}, [%4];"
                 : "=r"(a[0]), "=r"(a[1]), "=r"(a[2]), "=r"(a[3]) : "r"(addr));
}

DEVINL void mma_fp16(float c[4], const uint32_t a[4], uint32_t b0, uint32_t b1) {
    asm volatile(
        "mma.sync.aligned.m16n8k16.row.col.f32.f16.f16.f32 "
        "{%0,%1,%2,%3}, {%4,%5,%6,%7}, {%8,%9}, {%0,%1,%2,%3};"
        : "+f"(c[0]), "+f"(c[1]), "+f"(c[2]), "+f"(c[3])
        : "r"(a[0]), "r"(a[1]), "r"(a[2]), "r"(a[3]), "r"(b0), "r"(b1));
}

__global__ void __launch_bounds__(THREADS, 1)
axial_attn_kernel(const float* __restrict__ q, const float* __restrict__ k,
                  const float* __restrict__ v, float* __restrict__ out) {
    extern __shared__ char smem[];
    const uint32_t sb = smem_u32(smem);
    const int tid  = threadIdx.x;
    const int lane = tid & 31, w = tid >> 5;
    const int g = lane >> 2, t = lane & 3;

    // ---- CTA -> (batch, strip chunk). 152 = 24*5 + 8*4 ----
    int bx = blockIdx.x;
    int batch, cidx, ncta;
    if (bx < 120) { batch = bx / 5; cidx = bx - batch * 5; ncta = 5; }
    else { int r = bx - 120; int bb = r >> 2; batch = 24 + bb; cidx = r & 3; ncta = 4; }
    const int base = STRIPS_PER_BATCH / ncta, rem = STRIPS_PER_BATCH - base * ncta;
    int sstart, scnt;
    if (cidx < rem) { scnt = base + 1; sstart = cidx * scnt; }
    else            { scnt = base;     sstart = rem * (base + 1) + (cidx - rem) * base; }

    float* ksum = reinterpret_cast<float*>(smem + SM_KSUM);

    const float* kb = k + (size_t)batch * (128 * 128);
    const float* vb = v + (size_t)batch * (128 * 128);

    // ======== one-time fill: K (hi/lo, permuted contraction rows, + row sums), V (hi) ========
    // e4 = it*384 + tid: each warp covers 32 consecutive float4s = exactly one row.
    {
        const float4* kb4 = reinterpret_cast<const float4*>(kb);
        #pragma unroll
        for (int it = 0; it < 11; it++) {
            int e4  = it * THREADS + tid;
            int row = e4 >> 5;
            if (row < 128) {
                int col = (e4 & 31) << 2;
                float4 tk = kb4[e4];
                uint32_t h01, l01, h23, l23;
                split_pack2h(tk.x, tk.y, h01, l01);
                split_pack2h(tk.z, tk.w, h23, l23);
                uint32_t off = swz(kperm(row), col);
                *reinterpret_cast<uint2*>(smem + SM_KH + off) = make_uint2(h01, h23);
                *reinterpret_cast<uint2*>(smem + SM_KL + off) = make_uint2(l01, l23);
                float s = (tk.x + tk.y) + (tk.z + tk.w);
                s += __shfl_xor_sync(0xffffffffu, s, 16);
                s += __shfl_xor_sync(0xffffffffu, s, 8);
                s += __shfl_xor_sync(0xffffffffu, s, 4);
                s += __shfl_xor_sync(0xffffffffu, s, 2);
                s += __shfl_xor_sync(0xffffffffu, s, 1);
                if (lane == 0) ksum[row] = s;
            }
        }
        const float4* vb4 = reinterpret_cast<const float4*>(vb);
        #pragma unroll
        for (int it = 0; it < 11; it++) {
            int e4  = it * THREADS + tid;
            int row = e4 >> 5;
            if (row < 128) {
                int col = (e4 & 31) << 2;
                float4 tv = vb4[e4];
                uint32_t off = swz(row, col);
                *reinterpret_cast<uint2*>(smem + SM_VH + off) =
                    make_uint2(pack_hi2(tv.x, tv.y), pack_hi2(tv.z, tv.w));
            }
        }
    }
    __syncthreads();

    // ======== per-warp strip loop (32 rows x 128 cols; no barriers) ========
    // thread rows: g (m0 lo), g+8 (m0 hi), g+16 (m1 lo), g+24 (m1 hi)
    for (int s = w; s < scnt; s += NW) {
        const int r0 = (sstart + s) * 32;
        const float* qrw = q + ((size_t)batch * LSEQ + r0 + g) * 128 + 4 * t;

        float mloc[2][4], sloc[2][4];
        uint32_t A2[2][2][4][4];   // [phase][m][kk_local][reg] — unnormalized exp, fp16
        float qs[4];

        // ---- GEMM1 in two 64-col phases (online softmax) ----
        #pragma unroll
        for (int ph = 0; ph < 2; ph++) {
            float C1[2][8][4];     // [m][jt][i], 64 cols
            #pragma unroll
            for (int m = 0; m < 2; m++)
                #pragma unroll
                for (int jt = 0; jt < 8; jt++)
                    #pragma unroll
                    for (int i = 0; i < 4; i++) C1[m][jt][i] = 0.f;

            if (ph == 0) { qs[0] = qs[1] = qs[2] = qs[3] = 0.f; }

            #pragma unroll
            for (int kk = 0; kk < 8; kk++) {
                float4 qa = *reinterpret_cast<const float4*>(qrw + 16 * kk);
                float4 qb = *reinterpret_cast<const float4*>(qrw + 8 * 128 + 16 * kk);
                float4 qc = *reinterpret_cast<const float4*>(qrw + 16 * 128 + 16 * kk);
                float4 qd = *reinterpret_cast<const float4*>(qrw + 24 * 128 + 16 * kk);
                if (ph == 0) {
                    qs[0] += (qa.x + qa.y) + (qa.z + qa.w);
                    qs[1] += (qb.x + qb.y) + (qb.z + qb.w);
                    qs[2] += (qc.x + qc.y) + (qc.z + qc.w);
                    qs[3] += (qd.x + qd.y) + (qd.z + qd.w);
                }
                // scale by log2e before the split: MMA computes (log2e*Q)*K
                uint32_t A0h[4], A0l[4], A1h[4], A1l[4];
                split_pack2h(qa.x * LOG2E, qa.y * LOG2E, A0h[0], A0l[0]);
                split_pack2h(qb.x * LOG2E, qb.y * LOG2E, A0h[1], A0l[1]);
                split_pack2h(qa.z * LOG2E, qa.w * LOG2E, A0h[2], A0l[2]);
                split_pack2h(qb.z * LOG2E, qb.w * LOG2E, A0h[3], A0l[3]);
                split_pack2h(qc.x * LOG2E, qc.y * LOG2E, A1h[0], A1l[0]);
                split_pack2h(qd.x * LOG2E, qd.y * LOG2E, A1h[1], A1l[1]);
                split_pack2h(qc.z * LOG2E, qc.w * LOG2E, A1h[2], A1l[2]);
                split_pack2h(qd.z * LOG2E, qd.w * LOG2E, A1h[3], A1l[3]);

                #pragma unroll
                for (int jp = 0; jp < 4; jp++) {
                    const int c8 = 8 * ph + 2 * jp;
                    uint32_t bh[4], bl[4];
                    ldsm4t(bh, ldsm_addr(sb + SM_KH, 16 * kk, c8, lane));
                    ldsm4t(bl, ldsm_addr(sb + SM_KL, 16 * kk, c8, lane));
                    // m-block 0
                    mma_fp16(C1[0][2 * jp],     A0h, bh[0], bh[1]);
                    mma_fp16(C1[0][2 * jp + 1], A0h, bh[2], bh[3]);
                    mma_fp16(C1[0][2 * jp],     A0h, bl[0], bl[1]);
                    mma_fp16(C1[0][2 * jp + 1], A0h, bl[2], bl[3]);
                    mma_fp16(C1[0][2 * jp],     A0l, bh[0], bh[1]);
                    mma_fp16(C1[0][2 * jp + 1], A0l, bh[2], bh[3]);
                    // m-block 1 (same B fragments — the whole point)
                    mma_fp16(C1[1][2 * jp],     A1h, bh[0], bh[1]);
                    mma_fp16(C1[1][2 * jp + 1], A1h, bh[2], bh[3]);
                    mma_fp16(C1[1][2 * jp],     A1h, bl[0], bl[1]);
                    mma_fp16(C1[1][2 * jp + 1], A1h, bl[2], bl[3]);
                    mma_fp16(C1[1][2 * jp],     A1l, bh[0], bh[1]);
                    mma_fp16(C1[1][2 * jp + 1], A1l, bh[2], bh[3]);
                }
            }

            if (ph == 0) {
                #pragma unroll
                for (int r = 0; r < 4; r++) {
                    qs[r] += __shfl_xor_sync(0xffffffffu, qs[r], 1);
                    qs[r] += __shfl_xor_sync(0xffffffffu, qs[r], 2);
                    qs[r] *= LOG2E;     // rank-1 term in base-2 domain
                }
            }

            // ---- exact rank-1 term for this phase's 64 cols ----
            #pragma unroll
            for (int jt = 0; jt < 8; jt++) {
                float2 ks2 = *reinterpret_cast<const float2*>(ksum + 64 * ph + 8 * jt + 2 * t);
                C1[0][jt][0] += qs[0] * ks2.x;
                C1[0][jt][1] += qs[0] * ks2.y;
                C1[0][jt][2] += qs[1] * ks2.x;
                C1[0][jt][3] += qs[1] * ks2.y;
                C1[1][jt][0] += qs[2] * ks2.x;
                C1[1][jt][1] += qs[2] * ks2.y;
                C1[1][jt][2] += qs[3] * ks2.x;
                C1[1][jt][3] += qs[3] * ks2.y;
            }

            // ---- local softmax (base 2) over this phase's 64 cols ----
            #pragma unroll
            for (int m = 0; m < 2; m++) {
                float a = -3.4e38f, b = -3.4e38f;
                #pragma unroll
                for (int jt = 0; jt < 8; jt++) {
                    a = fmaxf(a, fmaxf(C1[m][jt][0], C1[m][jt][1]));
                    b = fmaxf(b, fmaxf(C1[m][jt][2], C1[m][jt][3]));
                }
                a = fmaxf(a, __shfl_xor_sync(0xffffffffu, a, 1));
                a = fmaxf(a, __shfl_xor_sync(0xffffffffu, a, 2));
                b = fmaxf(b, __shfl_xor_sync(0xffffffffu, b, 1));
                b = fmaxf(b, __shfl_xor_sync(0xffffffffu, b, 2));
                float sa = 0.f, sbv = 0.f;
                #pragma unroll
                for (int jt = 0; jt < 8; jt++) {
                    C1[m][jt][0] = ex2f(C1[m][jt][0] - a);
                    C1[m][jt][1] = ex2f(C1[m][jt][1] - a);
                    C1[m][jt][2] = ex2f(C1[m][jt][2] - b);
                    C1[m][jt][3] = ex2f(C1[m][jt][3] - b);
                    sa  += C1[m][jt][0] + C1[m][jt][1];
                    sbv += C1[m][jt][2] + C1[m][jt][3];
                }
                sa  += __shfl_xor_sync(0xffffffffu, sa, 1);
                sa  += __shfl_xor_sync(0xffffffffu, sa, 2);
                sbv += __shfl_xor_sync(0xffffffffu, sbv, 1);
                sbv += __shfl_xor_sync(0xffffffffu, sbv, 2);
                mloc[ph][2 * m]     = a;  sloc[ph][2 * m]     = sa;
                mloc[ph][2 * m + 1] = b;  sloc[ph][2 * m + 1] = sbv;
            }

            // ---- pack unnormalized exp as A-fragments (GEMM2 k-blocks 4*ph..4*ph+3) ----
            #pragma unroll
            for (int m = 0; m < 2; m++)
                #pragma unroll
                for (int kl = 0; kl < 4; kl++) {
                    A2[ph][m][kl][0] = pack_hi2(C1[m][2 * kl][0],     C1[m][2 * kl][1]);
                    A2[ph][m][kl][1] = pack_hi2(C1[m][2 * kl][2],     C1[m][2 * kl][3]);
                    A2[ph][m][kl][2] = pack_hi2(C1[m][2 * kl + 1][0], C1[m][2 * kl + 1][1]);
                    A2[ph][m][kl][3] = pack_hi2(C1[m][2 * kl + 1][2], C1[m][2 * kl + 1][3]);
                }
        }

        // ---- merge phases: per-row factors exp2(m_loc - M) / sum_total ----
        uint32_t F[2][2][2];   // [phase][m][rowhalf]
        #pragma unroll
        for (int r = 0; r < 4; r++) {
            const float M = fmaxf(mloc[0][r], mloc[1][r]);
            const float e0 = ex2f(mloc[0][r] - M);
            const float e1 = ex2f(mloc[1][r] - M);
            const float inv = 1.0f / (sloc[0][r] * e0 + sloc[1][r] * e1);
            const float f0 = e0 * inv, f1 = e1 * inv;
            F[0][r >> 1][r & 1] = pack_hi2(f0, f0);
            F[1][r >> 1][r & 1] = pack_hi2(f1, f1);
        }
        #pragma unroll
        for (int ph = 0; ph < 2; ph++)
            #pragma unroll
            for (int m = 0; m < 2; m++)
                #pragma unroll
                for (int kl = 0; kl < 4; kl++) {
                    A2[ph][m][kl][0] = hmul2u(A2[ph][m][kl][0], F[ph][m][0]);
                    A2[ph][m][kl][1] = hmul2u(A2[ph][m][kl][1], F[ph][m][1]);
                    A2[ph][m][kl][2] = hmul2u(A2[ph][m][kl][2], F[ph][m][0]);
                    A2[ph][m][kl][3] = hmul2u(A2[ph][m][kl][3], F[ph][m][1]);
                }

        // ---- GEMM2 in four 32-col d-quarters: O = P @ Vh (V frags shared by 2 m-blocks) ----
        #pragma unroll
        for (int dq = 0; dq < 4; dq++) {
            float C2[2][4][4];
            #pragma unroll
            for (int m = 0; m < 2; m++)
                #pragma unroll
                for (int jt = 0; jt < 4; jt++)
                    #pragma unroll
                    for (int i = 0; i < 4; i++) C2[m][jt][i] = 0.f;

            #pragma unroll
            for (int kk = 0; kk < 8; kk++) {
                const int ph = kk >> 2, kl = kk & 3;
                #pragma unroll
                for (int jp = 0; jp < 2; jp++) {
                    uint32_t bh[4];
                    ldsm4t(bh, ldsm_addr(sb + SM_VH, 16 * kk, 4 * dq + 2 * jp, lane));
                    mma_fp16(C2[0][2 * jp],     A2[ph][0][kl], bh[0], bh[1]);
                    mma_fp16(C2[0][2 * jp + 1], A2[ph][0][kl], bh[2], bh[3]);
                    mma_fp16(C2[1][2 * jp],     A2[ph][1][kl], bh[0], bh[1]);
                    mma_fp16(C2[1][2 * jp + 1], A2[ph][1][kl], bh[2], bh[3]);
                }
            }

            // ---- store this quarter ----
            #pragma unroll
            for (int m = 0; m < 2; m++) {
                float* og = out + ((size_t)batch * LSEQ + r0 + 16 * m) * 128 + 32 * dq;
                #pragma unroll
                for (int jt = 0; jt < 4; jt++) {
                    const int col = 8 * jt + 2 * t;
                    *reinterpret_cast<float2*>(og + (size_t)g * 128 + col) =
                        make_float2(C2[m][jt][0], C2[m][jt][1]);
                    *reinterpret_cast<float2*>(og + (size_t)(g + 8) * 128 + col) =
                        make_float2(C2[m][jt][2], C2[m][jt][3]);
                }
            }
        }
    }
}

} // anonymous namespace

extern "C" void kernel_launch(void* const* d_in, const int* in_sizes, int n_in,
                              void* d_out, int out_size) {
    const float* q = (const float*)d_in[0];
    const float* k = (const float*)d_in[1];
    const float* v = (const float*)d_in[2];
    float* out = (float*)d_out;

    cudaFuncSetAttribute(axial_attn_kernel,
                         cudaFuncAttributeMaxDynamicSharedMemorySize, SMEM_TOTAL);
    axial_attn_kernel<<<GRID, THREADS, SMEM_TOTAL>>>(q, k, v, out);
}